// round 12
// baseline (speedup 1.0000x reference)
#include <cuda_runtime.h>

typedef unsigned int u32;
typedef unsigned long long u64;

// ---- packed f32x2 helpers (Blackwell sm_103a) ------------------------------
__device__ __forceinline__ u64 pack2(float lo, float hi) {
    u64 r; asm("mov.b64 %0, {%1, %2};" : "=l"(r) : "f"(lo), "f"(hi)); return r;
}
__device__ __forceinline__ void unpack2(u64 v, float& lo, float& hi) {
    asm("mov.b64 {%0, %1}, %2;" : "=f"(lo), "=f"(hi) : "l"(v));
}
__device__ __forceinline__ void fma2(u64& d, u64 a, u64 b, u64 c) {
    asm("fma.rn.f32x2 %0, %1, %2, %3;" : "=l"(d) : "l"(a), "l"(b), "l"(c));
}

#define H2C 2654435761u
#define H3C 805459861u

// R11-calibrated dual-port split: gemm1/3/4 lower 32 out-cols const, upper 32
// smem; gemm2 ALL const; gemm5 const. All LDC warp-uniform (R8 rule).
#define OFF_S1 0
#define OFF_S2 2048
#define OFF_C1 3072
#define OFF_C2 5120
#define OFF_C3 9216
#define W_TOTAL 9408
__constant__ __align__(16) float CW[W_TOTAL];
__device__   __align__(16) float WPACK[W_TOTAL];

// enc scratch, k-chunk-major: ENC[j*CAP + i] = float4(enc[4j..4j+3]) of point i
#define CAP (1 << 20)
__device__ __align__(16) float4 ENC[8 * CAP];

__global__ void pack_weights(const float* __restrict__ s1,
                             const float* __restrict__ s2,
                             const float* __restrict__ c1,
                             const float* __restrict__ c2,
                             const float* __restrict__ c3) {
    int t = blockIdx.x * 256 + threadIdx.x;
    if (t >= W_TOTAL) return;
    float v;
    if      (t < OFF_S2) v = s1[t - OFF_S1];
    else if (t < OFF_C1) v = s2[t - OFF_S2];
    else if (t < OFF_C2) v = c1[t - OFF_C1];
    else if (t < OFF_C3) v = c2[t - OFF_C2];
    else                 v = c3[t - OFF_C3];
    WPACK[t] = v;
}

// ============================================================================
// K1: pure hash-grid gather (low regs, 256 thr -> co-resident with K2 blocks).
// ============================================================================
__global__ void gather_kernel(const float* __restrict__ xin,
                              const float* __restrict__ grids,
                              int base, int N)
{
    const int i = base + blockIdx.x * 256 + threadIdx.x;
    if (i >= N) return;

    const float px = __ldg(xin + (size_t)i * 19 + 0);
    const float py = __ldg(xin + (size_t)i * 19 + 1);
    const float pz = __ldg(xin + (size_t)i * 19 + 2);

    // res = ceil(16 * s^l), s = float32(2^0.4) (rounded up) => 65/257/1025 at
    // l=5/10/15. MAX_DIRECT = 2.
    const int RES_[16]  = {16,22,28,37,49,65,85,112,148,195,257,338,446,589,777,1025};
    const u32 SZ_[16]   = {4096u,10648u,21952u,50656u,117656u,274632u,
                           524288u,524288u,524288u,524288u,524288u,
                           524288u,524288u,524288u,524288u,524288u};

    float enc[32];
    #pragma unroll
    for (int l = 0; l < 16; l++) {
        const int R = RES_[l];
        const u32 S = SZ_[l];
        const float Rf = (float)R;
        float u = px * Rf, v = py * Rf, w = pz * Rf;
        float fu = floorf(u), fv = floorf(v), fw = floorf(w);
        float fx = u - fu, fy = v - fv, fz = w - fw;
        int ix = (int)fu, iy = (int)fv, iz = (int)fw;

        u32 idx[8];
        if (l <= 2) {
            #pragma unroll
            for (int j = 0; j < 8; j++) {
                int cx = ix + ((j >> 2) & 1);
                int cy = iy + ((j >> 1) & 1);
                int cz = iz + (j & 1);
                idx[j] = (u32)(cz * (R * R) + cy * R + cx) % S;
            }
        } else {
            u32 hx0 = (u32)ix;           u32 hx1 = hx0 + 1u;
            u32 hy0 = (u32)iy * H2C;     u32 hy1 = hy0 + H2C;
            u32 hz0 = (u32)iz * H3C;     u32 hz1 = hz0 + H3C;
            #pragma unroll
            for (int j = 0; j < 8; j++) {
                u32 h = ((j & 4) ? hx1 : hx0) ^ ((j & 2) ? hy1 : hy0) ^ ((j & 1) ? hz1 : hz0);
                idx[j] = (l >= 6) ? (h & 524287u) : (h % S);
            }
        }

        const float2* g = (const float2*)grids + (size_t)l * 524288u;
        float2 cc[8];
        #pragma unroll
        for (int j = 0; j < 8; j++) cc[j] = __ldg(g + idx[j]);

        const float gx = 1.f - fx, gy = 1.f - fy, gz = 1.f - fz;
        float c00x = cc[0].x*gx + cc[4].x*fx, c00y = cc[0].y*gx + cc[4].y*fx;
        float c01x = cc[1].x*gx + cc[5].x*fx, c01y = cc[1].y*gx + cc[5].y*fx;
        float c10x = cc[2].x*gx + cc[6].x*fx, c10y = cc[2].y*gx + cc[6].y*fx;
        float c11x = cc[3].x*gx + cc[7].x*fx, c11y = cc[3].y*gx + cc[7].y*fx;
        float c0x = c00x*gy + c10x*fy, c0y = c00y*gy + c10y*fy;
        float c1x = c01x*gy + c11x*fy, c1y = c01y*gy + c11y*fy;
        // NOTE: replicates reference bug: c0*(1-fz) + c1*fy   (fy, not fz!)
        enc[2*l]   = c0x*gz + c1x*fy;
        enc[2*l+1] = c0y*gz + c1y*fy;
    }

    #pragma unroll
    for (int j = 0; j < 8; j++)
        ENC[j * CAP + i] = make_float4(enc[4*j], enc[4*j+1], enc[4*j+2], enc[4*j+3]);
}

// ============================================================================
// K2: full MLP (R11 structure + port split), enc streamed from ENC.
// ============================================================================
__global__ void __launch_bounds__(128, 4) mlp_kernel(
    const float* __restrict__ xin,     // (N,19) (direc)
    const float* __restrict__ gw_s1,   // (32,64)
    const float* __restrict__ gw_c1,   // (32,64)
    const float* __restrict__ gw_c2,   // (64,64)
    float* __restrict__ out,           // (N,4)
    int base, int N)
{
    __shared__ __align__(16) ulonglong2 W1s[32 * 8];  // s1 cols 32..63
    __shared__ __align__(16) ulonglong2 W3s[32 * 8];  // c1 cols 32..63
    __shared__ __align__(16) ulonglong2 W4s[64 * 8];  // c2 cols 32..63
    __shared__ float sx[128 * 19];

    const int tid = threadIdx.x;
    const int blkbase = base + blockIdx.x * 128;
    {
        float* w1f = (float*)W1s;
        float* w3f = (float*)W3s;
        float* w4f = (float*)W4s;
        for (int t = tid; t < 1024; t += 128) {
            int r = t >> 5, c = t & 31;
            w1f[t] = gw_s1[r * 64 + 32 + c];
            w3f[t] = gw_c1[r * 64 + 32 + c];
        }
        for (int t = tid; t < 2048; t += 128) {
            int r = t >> 5, c = t & 31;
            w4f[t] = gw_c2[r * 64 + 32 + c];
        }
        const int gbase = blkbase * 19;
        const int lim   = N * 19;
        #pragma unroll
        for (int t = tid; t < 128 * 19; t += 128) {
            int g = gbase + t;
            sx[t] = (g < lim) ? xin[g] : 0.f;
        }
    }
    __syncthreads();

    const int i = blkbase + tid;
    if (i >= N) return;

    // ---- gemm1 (32x64), dual-port, enc streamed float4-at-a-time ------------
    u64 acc[32];
    #pragma unroll
    for (int j = 0; j < 32; j++) acc[j] = 0ull;
    const ulonglong2* W1c = (const ulonglong2*)(CW + OFF_S1);

    #pragma unroll
    for (int jj = 0; jj < 8; jj++) {
        float4 e = ENC[jj * CAP + i];
        float ek[4] = {e.x, e.y, e.z, e.w};
        #pragma unroll
        for (int t = 0; t < 4; t++) {
            int k = 4*jj + t;
            u64 a = pack2(ek[t], ek[t]);
            #pragma unroll
            for (int j = 0; j < 8; j++) {
                ulonglong2 wc = W1c[k*16 + j];
                fma2(acc[2*j],   a, wc.x, acc[2*j]);
                fma2(acc[2*j+1], a, wc.y, acc[2*j+1]);
                ulonglong2 ws = W1s[k*8 + j];
                fma2(acc[16+2*j],   a, ws.x, acc[16+2*j]);
                fma2(acc[16+2*j+1], a, ws.y, acc[16+2*j+1]);
            }
        }
    }

    // ---- relu(h1) folded into gemm2 (64x16), ALL const ----------------------
    u64 ovacc[8];
    #pragma unroll
    for (int j = 0; j < 8; j++) ovacc[j] = 0ull;
    const ulonglong2* W2c = (const ulonglong2*)(CW + OFF_S2);

    #pragma unroll
    for (int q = 0; q < 32; q++) {
        float lo, hi; unpack2(acc[q], lo, hi);
        lo = fmaxf(lo, 0.f); hi = fmaxf(hi, 0.f);
        int m = 2*q;
        u64 alo = pack2(lo, lo), ahi = pack2(hi, hi);
        #pragma unroll
        for (int j = 0; j < 4; j++) {
            ulonglong2 w0 = W2c[m*4 + j];
            ulonglong2 w1 = W2c[(m+1)*4 + j];
            fma2(ovacc[2*j],   alo, w0.x, ovacc[2*j]);
            fma2(ovacc[2*j+1], alo, w0.y, ovacc[2*j+1]);
            fma2(ovacc[2*j],   ahi, w1.x, ovacc[2*j]);
            fma2(ovacc[2*j+1], ahi, w1.y, ovacc[2*j+1]);
        }
    }
    float ov[16];
    #pragma unroll
    for (int j = 0; j < 8; j++) unpack2(ovacc[j], ov[2*j], ov[2*j+1]);
    const float sigma = ov[0];

    // ---- gemm3 (32x64), dual-port --------------------------------------------
    u64 acc3[32];
    #pragma unroll
    for (int j = 0; j < 32; j++) acc3[j] = 0ull;
    const ulonglong2* W3c = (const ulonglong2*)(CW + OFF_C1);
    const ulonglong2* W4c = (const ulonglong2*)(CW + OFF_C2);

    #pragma unroll
    for (int k = 0; k < 32; k++) {
        float cik = (k < 16) ? sx[tid*19 + 3 + k] : ov[k - 16];
        u64 a = pack2(cik, cik);
        #pragma unroll
        for (int j = 0; j < 8; j++) {
            ulonglong2 wc = W3c[k*16 + j];
            fma2(acc3[2*j],   a, wc.x, acc3[2*j]);
            fma2(acc3[2*j+1], a, wc.y, acc3[2*j+1]);
            ulonglong2 ws = W3s[k*8 + j];
            fma2(acc3[16+2*j],   a, ws.x, acc3[16+2*j]);
            fma2(acc3[16+2*j+1], a, ws.y, acc3[16+2*j+1]);
        }
    }

    // ---- relu(hc) streamed into gemm4 (64x64), dual-port ---------------------
    u64 a4[32];
    #pragma unroll
    for (int j = 0; j < 32; j++) a4[j] = 0ull;
    #pragma unroll
    for (int q = 0; q < 32; q++) {
        float lo, hi; unpack2(acc3[q], lo, hi);
        lo = fmaxf(lo, 0.f); hi = fmaxf(hi, 0.f);
        int m = 2*q;
        u64 alo = pack2(lo, lo), ahi = pack2(hi, hi);
        #pragma unroll
        for (int j = 0; j < 8; j++) {
            ulonglong2 w0 = W4c[m*16 + j];
            ulonglong2 w1 = W4c[(m+1)*16 + j];
            fma2(a4[2*j],   alo, w0.x, a4[2*j]);
            fma2(a4[2*j+1], alo, w0.y, a4[2*j+1]);
            fma2(a4[2*j],   ahi, w1.x, a4[2*j]);
            fma2(a4[2*j+1], ahi, w1.y, a4[2*j+1]);
            ulonglong2 s0 = W4s[m*8 + j];
            ulonglong2 s1v = W4s[(m+1)*8 + j];
            fma2(a4[16+2*j],   alo, s0.x,  a4[16+2*j]);
            fma2(a4[16+2*j+1], alo, s0.y,  a4[16+2*j+1]);
            fma2(a4[16+2*j],   ahi, s1v.x, a4[16+2*j]);
            fma2(a4[16+2*j+1], ahi, s1v.y, a4[16+2*j+1]);
        }
    }

    // ---- relu + gemm5 (64x3, const) + sigmoid ---------------------------------
    float col0 = 0.f, col1 = 0.f, col2 = 0.f;
    #pragma unroll
    for (int q = 0; q < 32; q++) {
        float lo, hi; unpack2(a4[q], lo, hi);
        lo = fmaxf(lo, 0.f); hi = fmaxf(hi, 0.f);
        int m = 2*q;
        col0 += lo * CW[OFF_C3 + m*3 + 0] + hi * CW[OFF_C3 + (m+1)*3 + 0];
        col1 += lo * CW[OFF_C3 + m*3 + 1] + hi * CW[OFF_C3 + (m+1)*3 + 1];
        col2 += lo * CW[OFF_C3 + m*3 + 2] + hi * CW[OFF_C3 + (m+1)*3 + 2];
    }

    col0 = 1.f / (1.f + expf(-col0));
    col1 = 1.f / (1.f + expf(-col1));
    col2 = 1.f / (1.f + expf(-col2));

    float4 r; r.x = col0; r.y = col1; r.z = col2; r.w = sigma;
    ((float4*)out)[i] = r;
}

#define NCHUNK 8

extern "C" void kernel_launch(void* const* d_in, const int* in_sizes, int n_in,
                              void* d_out, int out_size) {
    const float* x     = (const float*)d_in[0];
    const float* grids = (const float*)d_in[1];
    const float* ws1   = (const float*)d_in[2];
    const float* ws2   = (const float*)d_in[3];
    const float* wc1   = (const float*)d_in[4];
    const float* wc2   = (const float*)d_in[5];
    const float* wc3   = (const float*)d_in[6];
    float* out = (float*)d_out;

    const int N = in_sizes[0] / 19;

    // weights -> const bank (1 pack kernel + 1 memcpy node)
    pack_weights<<<(W_TOTAL + 255) / 256, 256>>>(ws1, ws2, wc1, wc2, wc3);
    void* wpack_ptr = nullptr;
    cudaGetSymbolAddress(&wpack_ptr, WPACK);
    cudaMemcpyToSymbolAsync(CW, wpack_ptr, W_TOTAL * sizeof(float), 0,
                            cudaMemcpyDeviceToDevice, 0);

    // Dual-stream chunked pipeline: K1(c) on stream 0, K2(c) on s1 after K1(c).
    // In steady state K1 (low-reg) and K2 (high-reg) blocks co-reside on each
    // SM (~28 warps vs 16 single-kernel) -> latency exposure drops.
    cudaStream_t s1;
    cudaStreamCreateWithFlags(&s1, cudaStreamNonBlocking);
    cudaEvent_t ev[NCHUNK], evJoin;
    for (int c = 0; c < NCHUNK; c++)
        cudaEventCreateWithFlags(&ev[c], cudaEventDisableTiming);
    cudaEventCreateWithFlags(&evJoin, cudaEventDisableTiming);

    const int chunk = (N + NCHUNK - 1) / NCHUNK;
    for (int c = 0; c < NCHUNK; c++) {
        int base = c * chunk;
        int cnt  = (base + chunk <= N) ? chunk : (N - base);
        if (cnt <= 0) break;
        gather_kernel<<<(cnt + 255) / 256, 256, 0, 0>>>(x, grids, base, N);
        cudaEventRecord(ev[c], 0);
        cudaStreamWaitEvent(s1, ev[c], 0);
        mlp_kernel<<<(cnt + 127) / 128, 128, 0, s1>>>(x, ws1, wc1, wc2, out, base, N);
    }
    // join s1 back into the capture origin stream
    cudaEventRecord(evJoin, s1);
    cudaStreamWaitEvent(0, evJoin, 0);

    for (int c = 0; c < NCHUNK; c++) cudaEventDestroy(ev[c]);
    cudaEventDestroy(evJoin);
    cudaStreamDestroy(s1);
}

// round 13
// speedup vs baseline: 1.3811x; 1.3811x over previous
#include <cuda_runtime.h>

typedef unsigned int u32;
typedef unsigned long long u64;

// ---- packed f32x2 helpers (Blackwell sm_103a) ------------------------------
__device__ __forceinline__ u64 pack2(float lo, float hi) {
    u64 r; asm("mov.b64 %0, {%1, %2};" : "=l"(r) : "f"(lo), "f"(hi)); return r;
}
__device__ __forceinline__ void unpack2(u64 v, float& lo, float& hi) {
    asm("mov.b64 {%0, %1}, %2;" : "=f"(lo), "=f"(hi) : "l"(v));
}
__device__ __forceinline__ void fma2(u64& d, u64 a, u64 b, u64 c) {
    asm("fma.rn.f32x2 %0, %1, %2, %3;" : "=l"(d) : "l"(a), "l"(b), "l"(c));
}

#define H2C 2654435761u
#define H3C 805459861u

// R11-calibrated dual-port split: gemm1/3/4 lower 32 out-cols const, upper 32
// smem; gemm2 ALL const; gemm5 const. All LDC warp-uniform (R8 rule).
#define OFF_S1 0
#define OFF_S2 2048
#define OFF_C1 3072
#define OFF_C2 5120
#define OFF_C3 9216
#define W_TOTAL 9408
__constant__ __align__(16) float CW[W_TOTAL];
__device__   __align__(16) float WPACK[W_TOTAL];

__global__ void pack_weights(const float* __restrict__ s1,
                             const float* __restrict__ s2,
                             const float* __restrict__ c1,
                             const float* __restrict__ c2,
                             const float* __restrict__ c3) {
    int t = blockIdx.x * 256 + threadIdx.x;
    if (t >= W_TOTAL) return;
    float v;
    if      (t < OFF_S2) v = s1[t - OFF_S1];
    else if (t < OFF_C1) v = s2[t - OFF_S2];
    else if (t < OFF_C2) v = c1[t - OFF_C1];
    else if (t < OFF_C3) v = c2[t - OFF_C2];
    else                 v = c3[t - OFF_C3];
    WPACK[t] = v;
}

// res = ceil(16 * s^l), s = float32(2^0.4) (rounded up) => 65/257/1025 at
// l=5/10/15. MAX_DIRECT = 2.
__device__ __forceinline__ void level_load(int l, float px, float py, float pz,
                                           const float* __restrict__ grids,
                                           float2* cc)
{
    const int RES_[16]  = {16,22,28,37,49,65,85,112,148,195,257,338,446,589,777,1025};
    const u32 SZ_[16]   = {4096u,10648u,21952u,50656u,117656u,274632u,
                           524288u,524288u,524288u,524288u,524288u,
                           524288u,524288u,524288u,524288u,524288u};
    const int R = RES_[l];
    const u32 S = SZ_[l];
    const float Rf = (float)R;
    int ix = (int)floorf(px * Rf);
    int iy = (int)floorf(py * Rf);
    int iz = (int)floorf(pz * Rf);

    u32 idx[8];
    if (l <= 2) {
        #pragma unroll
        for (int j = 0; j < 8; j++) {
            int cx = ix + ((j >> 2) & 1);
            int cy = iy + ((j >> 1) & 1);
            int cz = iz + (j & 1);
            idx[j] = (u32)(cz * (R * R) + cy * R + cx) % S;
        }
    } else {
        u32 hx0 = (u32)ix;           u32 hx1 = hx0 + 1u;
        u32 hy0 = (u32)iy * H2C;     u32 hy1 = hy0 + H2C;
        u32 hz0 = (u32)iz * H3C;     u32 hz1 = hz0 + H3C;
        #pragma unroll
        for (int j = 0; j < 8; j++) {
            u32 h = ((j & 4) ? hx1 : hx0) ^ ((j & 2) ? hy1 : hy0) ^ ((j & 1) ? hz1 : hz0);
            idx[j] = (l >= 6) ? (h & 524287u) : (h % S);
        }
    }

    const float2* g = (const float2*)grids + (size_t)l * 524288u;
    #pragma unroll
    for (int j = 0; j < 8; j++) cc[j] = __ldg(g + idx[j]);
}

__global__ void __launch_bounds__(128, 4) nerf_fused(
    const float* __restrict__ xin,     // (N,19)
    const float* __restrict__ grids,   // (16, 524288, 2)
    const float* __restrict__ gw_s1,   // (32,64)
    const float* __restrict__ gw_s2,   // unused (gemm2 all const)
    const float* __restrict__ gw_c1,   // (32,64)
    const float* __restrict__ gw_c2,   // (64,64)
    float* __restrict__ out,           // (N,4)
    int N)
{
    __shared__ __align__(16) ulonglong2 W1s[32 * 8];  // s1 cols 32..63
    __shared__ __align__(16) ulonglong2 W3s[32 * 8];  // c1 cols 32..63
    __shared__ __align__(16) ulonglong2 W4s[64 * 8];  // c2 cols 32..63
    __shared__ float sx[128 * 19];                    // staged xin (19 coprime 32)

    const int tid = threadIdx.x;
    {
        float* w1f = (float*)W1s;
        float* w3f = (float*)W3s;
        float* w4f = (float*)W4s;
        for (int t = tid; t < 1024; t += 128) {
            int r = t >> 5, c = t & 31;
            w1f[t] = gw_s1[r * 64 + 32 + c];
            w3f[t] = gw_c1[r * 64 + 32 + c];
        }
        for (int t = tid; t < 2048; t += 128) {
            int r = t >> 5, c = t & 31;
            w4f[t] = gw_c2[r * 64 + 32 + c];
        }
        const int base = blockIdx.x * (128 * 19);
        const int lim  = N * 19;
        #pragma unroll
        for (int t = tid; t < 128 * 19; t += 128) {
            int g = base + t;
            sx[t] = (g < lim) ? xin[g] : 0.f;
        }
    }
    __syncthreads();

    const int i = blockIdx.x * 128 + tid;
    if (i >= N) return;

    const float px = sx[tid * 19 + 0];
    const float py = sx[tid * 19 + 1];
    const float pz = sx[tid * 19 + 2];

    const int RES_[16] = {16,22,28,37,49,65,85,112,148,195,257,338,446,589,777,1025};

    // ---- phase A: gather FUSED with gemm1, distance-1 pipelined loads -------
    // Level l+1's 8 LDG are issued BEFORE level l's lerp+gemm block, so each
    // level's L2 latency is covered by ~90 issued instrs of lerp+FMA+weight
    // loads (x4 warps RR). R9 pipelined without fusion (no cover, 882us);
    // R11 fused without pipelining (cover after the consume, 820us).
    u64 acc[32];
    #pragma unroll
    for (int j = 0; j < 32; j++) acc[j] = 0ull;
    const ulonglong2* W1c = (const ulonglong2*)(CW + OFF_S1);

    float2 ccA[8], ccB[8];
    level_load(0, px, py, pz, grids, ccA);

    #pragma unroll
    for (int l = 0; l < 16; l += 2) {
        // prefetch odd level while even level computes
        level_load(l + 1, px, py, pz, grids, ccB);

        #pragma unroll
        for (int half = 0; half < 2; half++) {
            const int lv = l + half;
            const float2* cc = half ? ccB : ccA;

            // prefetch next even level while odd level computes
            if (half == 1 && l + 2 < 16)
                level_load(l + 2, px, py, pz, grids, ccA);

            const float Rf = (float)RES_[lv];
            float u = px * Rf, v = py * Rf, w = pz * Rf;
            float fx = u - floorf(u), fy = v - floorf(v), fz = w - floorf(w);
            const float gx = 1.f - fx, gy = 1.f - fy, gz = 1.f - fz;
            float c00x = cc[0].x*gx + cc[4].x*fx, c00y = cc[0].y*gx + cc[4].y*fx;
            float c01x = cc[1].x*gx + cc[5].x*fx, c01y = cc[1].y*gx + cc[5].y*fx;
            float c10x = cc[2].x*gx + cc[6].x*fx, c10y = cc[2].y*gx + cc[6].y*fx;
            float c11x = cc[3].x*gx + cc[7].x*fx, c11y = cc[3].y*gx + cc[7].y*fx;
            float c0x = c00x*gy + c10x*fy, c0y = c00y*gy + c10y*fy;
            float c1x = c01x*gy + c11x*fy, c1y = c01y*gy + c11y*fy;
            // NOTE: replicates reference bug: c0*(1-fz) + c1*fy  (fy, not fz!)
            float fex = c0x*gz + c1x*fy;
            float fey = c0y*gz + c1y*fy;

            // gemm1 partial: k = 2*lv and 2*lv+1, dual-port
            u64 a0 = pack2(fex, fex);
            u64 a1 = pack2(fey, fey);
            #pragma unroll
            for (int j = 0; j < 8; j++) {
                ulonglong2 w0 = W1c[(2*lv)   * 16 + j];    // cols 4j..4j+3
                ulonglong2 w1 = W1c[(2*lv+1) * 16 + j];
                fma2(acc[2*j],   a0, w0.x, acc[2*j]);
                fma2(acc[2*j+1], a0, w0.y, acc[2*j+1]);
                fma2(acc[2*j],   a1, w1.x, acc[2*j]);
                fma2(acc[2*j+1], a1, w1.y, acc[2*j+1]);
                ulonglong2 s0 = W1s[(2*lv)   * 8 + j];     // cols 32+4j..+3
                ulonglong2 s1v = W1s[(2*lv+1) * 8 + j];
                fma2(acc[16+2*j],   a0, s0.x,  acc[16+2*j]);
                fma2(acc[16+2*j+1], a0, s0.y,  acc[16+2*j+1]);
                fma2(acc[16+2*j],   a1, s1v.x, acc[16+2*j]);
                fma2(acc[16+2*j+1], a1, s1v.y, acc[16+2*j+1]);
            }
        }
    }

    // ---- relu(h1) folded into gemm2 (64x16), ALL const ----------------------
    u64 ovacc[8];
    #pragma unroll
    for (int j = 0; j < 8; j++) ovacc[j] = 0ull;
    const ulonglong2* W2c = (const ulonglong2*)(CW + OFF_S2);

    #pragma unroll
    for (int q = 0; q < 32; q++) {
        float lo, hi; unpack2(acc[q], lo, hi);
        lo = fmaxf(lo, 0.f); hi = fmaxf(hi, 0.f);
        int m = 2*q;            // q<16: cols 2q; q>=16: cols 32+2(q-16) == 2q
        u64 alo = pack2(lo, lo), ahi = pack2(hi, hi);
        #pragma unroll
        for (int j = 0; j < 4; j++) {
            ulonglong2 w0 = W2c[m*4 + j];
            ulonglong2 w1 = W2c[(m+1)*4 + j];
            fma2(ovacc[2*j],   alo, w0.x, ovacc[2*j]);
            fma2(ovacc[2*j+1], alo, w0.y, ovacc[2*j+1]);
            fma2(ovacc[2*j],   ahi, w1.x, ovacc[2*j]);
            fma2(ovacc[2*j+1], ahi, w1.y, ovacc[2*j+1]);
        }
    }
    float ov[16];
    #pragma unroll
    for (int j = 0; j < 8; j++) unpack2(ovacc[j], ov[2*j], ov[2*j+1]);
    const float sigma = ov[0];

    // ---- gemm3 (32x64), dual-port -------------------------------------------
    u64 acc3[32];
    #pragma unroll
    for (int j = 0; j < 32; j++) acc3[j] = 0ull;
    const ulonglong2* W3c = (const ulonglong2*)(CW + OFF_C1);
    const ulonglong2* W4c = (const ulonglong2*)(CW + OFF_C2);

    #pragma unroll
    for (int k = 0; k < 32; k++) {
        float cik = (k < 16) ? sx[tid*19 + 3 + k] : ov[k - 16];
        u64 a = pack2(cik, cik);
        #pragma unroll
        for (int j = 0; j < 8; j++) {
            ulonglong2 wc = W3c[k*16 + j];
            fma2(acc3[2*j],   a, wc.x, acc3[2*j]);
            fma2(acc3[2*j+1], a, wc.y, acc3[2*j+1]);
            ulonglong2 ws = W3s[k*8 + j];
            fma2(acc3[16+2*j],   a, ws.x, acc3[16+2*j]);
            fma2(acc3[16+2*j+1], a, ws.y, acc3[16+2*j+1]);
        }
    }

    // ---- relu(hc) streamed into gemm4 (64x64), dual-port --------------------
    u64 a4[32];
    #pragma unroll
    for (int j = 0; j < 32; j++) a4[j] = 0ull;
    #pragma unroll
    for (int q = 0; q < 32; q++) {
        float lo, hi; unpack2(acc3[q], lo, hi);
        lo = fmaxf(lo, 0.f); hi = fmaxf(hi, 0.f);
        int m = 2*q;
        u64 alo = pack2(lo, lo), ahi = pack2(hi, hi);
        #pragma unroll
        for (int j = 0; j < 8; j++) {
            ulonglong2 w0 = W4c[m*16 + j];
            ulonglong2 w1 = W4c[(m+1)*16 + j];
            fma2(a4[2*j],   alo, w0.x, a4[2*j]);
            fma2(a4[2*j+1], alo, w0.y, a4[2*j+1]);
            fma2(a4[2*j],   ahi, w1.x, a4[2*j]);
            fma2(a4[2*j+1], ahi, w1.y, a4[2*j+1]);
            ulonglong2 s0 = W4s[m*8 + j];
            ulonglong2 s1v = W4s[(m+1)*8 + j];
            fma2(a4[16+2*j],   alo, s0.x,  a4[16+2*j]);
            fma2(a4[16+2*j+1], alo, s0.y,  a4[16+2*j+1]);
            fma2(a4[16+2*j],   ahi, s1v.x, a4[16+2*j]);
            fma2(a4[16+2*j+1], ahi, s1v.y, a4[16+2*j+1]);
        }
    }

    // ---- relu + gemm5 (64x3, const) + sigmoid -------------------------------
    float col0 = 0.f, col1 = 0.f, col2 = 0.f;
    #pragma unroll
    for (int q = 0; q < 32; q++) {
        float lo, hi; unpack2(a4[q], lo, hi);
        lo = fmaxf(lo, 0.f); hi = fmaxf(hi, 0.f);
        int m = 2*q;
        col0 += lo * CW[OFF_C3 + m*3 + 0] + hi * CW[OFF_C3 + (m+1)*3 + 0];
        col1 += lo * CW[OFF_C3 + m*3 + 1] + hi * CW[OFF_C3 + (m+1)*3 + 1];
        col2 += lo * CW[OFF_C3 + m*3 + 2] + hi * CW[OFF_C3 + (m+1)*3 + 2];
    }

    col0 = 1.f / (1.f + expf(-col0));
    col1 = 1.f / (1.f + expf(-col1));
    col2 = 1.f / (1.f + expf(-col2));

    float4 r; r.x = col0; r.y = col1; r.z = col2; r.w = sigma;
    ((float4*)out)[i] = r;
}

extern "C" void kernel_launch(void* const* d_in, const int* in_sizes, int n_in,
                              void* d_out, int out_size) {
    const float* x     = (const float*)d_in[0];
    const float* grids = (const float*)d_in[1];
    const float* ws1   = (const float*)d_in[2];
    const float* ws2   = (const float*)d_in[3];
    const float* wc1   = (const float*)d_in[4];
    const float* wc2   = (const float*)d_in[5];
    const float* wc3   = (const float*)d_in[6];
    float* out = (float*)d_out;

    // pack all weights into one device buffer, then ONE memcpy node to const.
    pack_weights<<<(W_TOTAL + 255) / 256, 256>>>(ws1, ws2, wc1, wc2, wc3);
    void* wpack_ptr = nullptr;
    cudaGetSymbolAddress(&wpack_ptr, WPACK);
    cudaMemcpyToSymbolAsync(CW, wpack_ptr, W_TOTAL * sizeof(float), 0,
                            cudaMemcpyDeviceToDevice, 0);

    const int N = in_sizes[0] / 19;
    const int blocks = (N + 127) / 128;
    nerf_fused<<<blocks, 128>>>(x, grids, ws1, ws2, wc1, wc2, out, N);
}

// round 14
// speedup vs baseline: 1.3828x; 1.0013x over previous
#include <cuda_runtime.h>

typedef unsigned int u32;
typedef unsigned long long u64;

// ---- packed f32x2 helpers (Blackwell sm_103a) ------------------------------
__device__ __forceinline__ u64 pack2(float lo, float hi) {
    u64 r; asm("mov.b64 %0, {%1, %2};" : "=l"(r) : "f"(lo), "f"(hi)); return r;
}
__device__ __forceinline__ void unpack2(u64 v, float& lo, float& hi) {
    asm("mov.b64 {%0, %1}, %2;" : "=f"(lo), "=f"(hi) : "l"(v));
}
__device__ __forceinline__ void fma2(u64& d, u64 a, u64 b, u64 c) {
    asm("fma.rn.f32x2 %0, %1, %2, %3;" : "=l"(d) : "l"(a), "l"(b), "l"(c));
}

#define H2C 2654435761u
#define H3C 805459861u

// R14-recalibrated dual-port split (const kappa=13.4 cyc/u128/SMSP measured
// R2; LDS broadcast lambda_eff~1.0 cyc/u128/SM measured R13):
//   gemm1/3: 8 const + 8 smem col-groups (cols 0..31 / 32..63)
//   gemm2:   ALL const
//   gemm4:   4 const + 12 smem col-groups (cols 0..15 / 16..63)  <- R14 delta
//   gemm5:   const
// -> const ~1024 u128 (~760k cyc), L1 ~745k cyc: balanced.
// All LDC warp-uniform (divergent LDC catastrophic, R8).
#define OFF_S1 0
#define OFF_S2 2048
#define OFF_C1 3072
#define OFF_C2 5120
#define OFF_C3 9216
#define W_TOTAL 9408
__constant__ __align__(16) float CW[W_TOTAL];
__device__   __align__(16) float WPACK[W_TOTAL];

__global__ void pack_weights(const float* __restrict__ s1,
                             const float* __restrict__ s2,
                             const float* __restrict__ c1,
                             const float* __restrict__ c2,
                             const float* __restrict__ c3) {
    int t = blockIdx.x * 256 + threadIdx.x;
    if (t >= W_TOTAL) return;
    float v;
    if      (t < OFF_S2) v = s1[t - OFF_S1];
    else if (t < OFF_C1) v = s2[t - OFF_S2];
    else if (t < OFF_C2) v = c1[t - OFF_C1];
    else if (t < OFF_C3) v = c2[t - OFF_C2];
    else                 v = c3[t - OFF_C3];
    WPACK[t] = v;
}

// res = ceil(16 * s^l), s = float32(2^0.4) (rounded up) => 65/257/1025 at
// l=5/10/15. MAX_DIRECT = 2.
__device__ __forceinline__ void level_load(int l, float px, float py, float pz,
                                           const float* __restrict__ grids,
                                           float2* cc)
{
    const int RES_[16]  = {16,22,28,37,49,65,85,112,148,195,257,338,446,589,777,1025};
    const u32 SZ_[16]   = {4096u,10648u,21952u,50656u,117656u,274632u,
                           524288u,524288u,524288u,524288u,524288u,
                           524288u,524288u,524288u,524288u,524288u};
    const int R = RES_[l];
    const u32 S = SZ_[l];
    const float Rf = (float)R;
    int ix = (int)floorf(px * Rf);
    int iy = (int)floorf(py * Rf);
    int iz = (int)floorf(pz * Rf);

    u32 idx[8];
    if (l <= 2) {
        #pragma unroll
        for (int j = 0; j < 8; j++) {
            int cx = ix + ((j >> 2) & 1);
            int cy = iy + ((j >> 1) & 1);
            int cz = iz + (j & 1);
            idx[j] = (u32)(cz * (R * R) + cy * R + cx) % S;
        }
    } else {
        u32 hx0 = (u32)ix;           u32 hx1 = hx0 + 1u;
        u32 hy0 = (u32)iy * H2C;     u32 hy1 = hy0 + H2C;
        u32 hz0 = (u32)iz * H3C;     u32 hz1 = hz0 + H3C;
        #pragma unroll
        for (int j = 0; j < 8; j++) {
            u32 h = ((j & 4) ? hx1 : hx0) ^ ((j & 2) ? hy1 : hy0) ^ ((j & 1) ? hz1 : hz0);
            idx[j] = (l >= 6) ? (h & 524287u) : (h % S);
        }
    }

    const float2* g = (const float2*)grids + (size_t)l * 524288u;
    #pragma unroll
    for (int j = 0; j < 8; j++) cc[j] = __ldg(g + idx[j]);
}

__global__ void __launch_bounds__(128, 4) nerf_fused(
    const float* __restrict__ xin,     // (N,19)
    const float* __restrict__ grids,   // (16, 524288, 2)
    const float* __restrict__ gw_s1,   // (32,64)
    const float* __restrict__ gw_s2,   // unused (gemm2 all const)
    const float* __restrict__ gw_c1,   // (32,64)
    const float* __restrict__ gw_c2,   // (64,64)
    float* __restrict__ out,           // (N,4)
    int N)
{
    __shared__ __align__(16) ulonglong2 W1s[32 * 8];   // s1 cols 32..63
    __shared__ __align__(16) ulonglong2 W3s[32 * 8];   // c1 cols 32..63
    __shared__ __align__(16) ulonglong2 W4s[64 * 12];  // c2 cols 16..63
    __shared__ float sx[128 * 19];                     // staged xin

    const int tid = threadIdx.x;
    {
        float* w1f = (float*)W1s;
        float* w3f = (float*)W3s;
        float* w4f = (float*)W4s;
        for (int t = tid; t < 1024; t += 128) {
            int r = t >> 5, c = t & 31;
            w1f[t] = gw_s1[r * 64 + 32 + c];
            w3f[t] = gw_c1[r * 64 + 32 + c];
        }
        for (int t = tid; t < 3072; t += 128) {        // 64 rows x 48 cols (16..63)
            int r = t / 48, c = t % 48;
            w4f[t] = gw_c2[r * 64 + 16 + c];
        }
        const int base = blockIdx.x * (128 * 19);
        const int lim  = N * 19;
        #pragma unroll
        for (int t = tid; t < 128 * 19; t += 128) {
            int g = base + t;
            sx[t] = (g < lim) ? xin[g] : 0.f;
        }
    }
    __syncthreads();

    const int i = blockIdx.x * 128 + tid;
    if (i >= N) return;

    const float px = sx[tid * 19 + 0];
    const float py = sx[tid * 19 + 1];
    const float pz = sx[tid * 19 + 2];

    const int RES_[16] = {16,22,28,37,49,65,85,112,148,195,257,338,446,589,777,1025};

    // ---- phase A: gather FUSED with gemm1, distance-1 pipelined loads (R13) -
    u64 acc[32];
    #pragma unroll
    for (int j = 0; j < 32; j++) acc[j] = 0ull;
    const ulonglong2* W1c = (const ulonglong2*)(CW + OFF_S1);

    float2 ccA[8], ccB[8];
    level_load(0, px, py, pz, grids, ccA);

    #pragma unroll
    for (int l = 0; l < 16; l += 2) {
        level_load(l + 1, px, py, pz, grids, ccB);

        #pragma unroll
        for (int half = 0; half < 2; half++) {
            const int lv = l + half;
            const float2* cc = half ? ccB : ccA;

            if (half == 1 && l + 2 < 16)
                level_load(l + 2, px, py, pz, grids, ccA);

            const float Rf = (float)RES_[lv];
            float u = px * Rf, v = py * Rf, w = pz * Rf;
            float fx = u - floorf(u), fy = v - floorf(v), fz = w - floorf(w);
            const float gx = 1.f - fx, gy = 1.f - fy, gz = 1.f - fz;
            float c00x = cc[0].x*gx + cc[4].x*fx, c00y = cc[0].y*gx + cc[4].y*fx;
            float c01x = cc[1].x*gx + cc[5].x*fx, c01y = cc[1].y*gx + cc[5].y*fx;
            float c10x = cc[2].x*gx + cc[6].x*fx, c10y = cc[2].y*gx + cc[6].y*fx;
            float c11x = cc[3].x*gx + cc[7].x*fx, c11y = cc[3].y*gx + cc[7].y*fx;
            float c0x = c00x*gy + c10x*fy, c0y = c00y*gy + c10y*fy;
            float c1x = c01x*gy + c11x*fy, c1y = c01y*gy + c11y*fy;
            // NOTE: replicates reference bug: c0*(1-fz) + c1*fy  (fy, not fz!)
            float fex = c0x*gz + c1x*fy;
            float fey = c0y*gz + c1y*fy;

            u64 a0 = pack2(fex, fex);
            u64 a1 = pack2(fey, fey);
            #pragma unroll
            for (int j = 0; j < 8; j++) {
                ulonglong2 w0 = W1c[(2*lv)   * 16 + j];    // cols 4j..4j+3
                ulonglong2 w1 = W1c[(2*lv+1) * 16 + j];
                fma2(acc[2*j],   a0, w0.x, acc[2*j]);
                fma2(acc[2*j+1], a0, w0.y, acc[2*j+1]);
                fma2(acc[2*j],   a1, w1.x, acc[2*j]);
                fma2(acc[2*j+1], a1, w1.y, acc[2*j+1]);
                ulonglong2 s0 = W1s[(2*lv)   * 8 + j];     // cols 32+4j..+3
                ulonglong2 s1v = W1s[(2*lv+1) * 8 + j];
                fma2(acc[16+2*j],   a0, s0.x,  acc[16+2*j]);
                fma2(acc[16+2*j+1], a0, s0.y,  acc[16+2*j+1]);
                fma2(acc[16+2*j],   a1, s1v.x, acc[16+2*j]);
                fma2(acc[16+2*j+1], a1, s1v.y, acc[16+2*j+1]);
            }
        }
    }

    // ---- relu(h1) folded into gemm2 (64x16), ALL const ----------------------
    u64 ovacc[8];
    #pragma unroll
    for (int j = 0; j < 8; j++) ovacc[j] = 0ull;
    const ulonglong2* W2c = (const ulonglong2*)(CW + OFF_S2);

    #pragma unroll
    for (int q = 0; q < 32; q++) {
        float lo, hi; unpack2(acc[q], lo, hi);
        lo = fmaxf(lo, 0.f); hi = fmaxf(hi, 0.f);
        int m = 2*q;
        u64 alo = pack2(lo, lo), ahi = pack2(hi, hi);
        #pragma unroll
        for (int j = 0; j < 4; j++) {
            ulonglong2 w0 = W2c[m*4 + j];
            ulonglong2 w1 = W2c[(m+1)*4 + j];
            fma2(ovacc[2*j],   alo, w0.x, ovacc[2*j]);
            fma2(ovacc[2*j+1], alo, w0.y, ovacc[2*j+1]);
            fma2(ovacc[2*j],   ahi, w1.x, ovacc[2*j]);
            fma2(ovacc[2*j+1], ahi, w1.y, ovacc[2*j+1]);
        }
    }
    float ov[16];
    #pragma unroll
    for (int j = 0; j < 8; j++) unpack2(ovacc[j], ov[2*j], ov[2*j+1]);
    const float sigma = ov[0];

    // ---- gemm3 (32x64), dual-port -------------------------------------------
    u64 acc3[32];
    #pragma unroll
    for (int j = 0; j < 32; j++) acc3[j] = 0ull;
    const ulonglong2* W3c = (const ulonglong2*)(CW + OFF_C1);
    const ulonglong2* W4c = (const ulonglong2*)(CW + OFF_C2);

    #pragma unroll
    for (int k = 0; k < 32; k++) {
        float cik = (k < 16) ? sx[tid*19 + 3 + k] : ov[k - 16];
        u64 a = pack2(cik, cik);
        #pragma unroll
        for (int j = 0; j < 8; j++) {
            ulonglong2 wc = W3c[k*16 + j];
            fma2(acc3[2*j],   a, wc.x, acc3[2*j]);
            fma2(acc3[2*j+1], a, wc.y, acc3[2*j+1]);
            ulonglong2 ws = W3s[k*8 + j];
            fma2(acc3[16+2*j],   a, ws.x, acc3[16+2*j]);
            fma2(acc3[16+2*j+1], a, ws.y, acc3[16+2*j+1]);
        }
    }

    // ---- relu(hc) streamed into gemm4 (64x64): 4 const + 12 smem groups -----
    // a4[q] accumulates out cols (2q, 2q+1): q<8 via const (cols 0..15),
    // q>=8 via smem (cols 16..63; 16+2(q-8) == 2q).
    u64 a4[32];
    #pragma unroll
    for (int j = 0; j < 32; j++) a4[j] = 0ull;
    #pragma unroll
    for (int q = 0; q < 32; q++) {
        float lo, hi; unpack2(acc3[q], lo, hi);
        lo = fmaxf(lo, 0.f); hi = fmaxf(hi, 0.f);
        int m = 2*q;
        u64 alo = pack2(lo, lo), ahi = pack2(hi, hi);
        #pragma unroll
        for (int j = 0; j < 4; j++) {                  // const: cols 4j..4j+3
            ulonglong2 w0 = W4c[m*16 + j];
            ulonglong2 w1 = W4c[(m+1)*16 + j];
            fma2(a4[2*j],   alo, w0.x, a4[2*j]);
            fma2(a4[2*j+1], alo, w0.y, a4[2*j+1]);
            fma2(a4[2*j],   ahi, w1.x, a4[2*j]);
            fma2(a4[2*j+1], ahi, w1.y, a4[2*j+1]);
        }
        #pragma unroll
        for (int j = 0; j < 12; j++) {                 // smem: cols 16+4j..+3
            ulonglong2 s0 = W4s[m*12 + j];
            ulonglong2 s1v = W4s[(m+1)*12 + j];
            fma2(a4[8+2*j],   alo, s0.x,  a4[8+2*j]);
            fma2(a4[8+2*j+1], alo, s0.y,  a4[8+2*j+1]);
            fma2(a4[8+2*j],   ahi, s1v.x, a4[8+2*j]);
            fma2(a4[8+2*j+1], ahi, s1v.y, a4[8+2*j+1]);
        }
    }

    // ---- relu + gemm5 (64x3, const) + sigmoid -------------------------------
    float col0 = 0.f, col1 = 0.f, col2 = 0.f;
    #pragma unroll
    for (int q = 0; q < 32; q++) {
        float lo, hi; unpack2(a4[q], lo, hi);
        lo = fmaxf(lo, 0.f); hi = fmaxf(hi, 0.f);
        int m = 2*q;
        col0 += lo * CW[OFF_C3 + m*3 + 0] + hi * CW[OFF_C3 + (m+1)*3 + 0];
        col1 += lo * CW[OFF_C3 + m*3 + 1] + hi * CW[OFF_C3 + (m+1)*3 + 1];
        col2 += lo * CW[OFF_C3 + m*3 + 2] + hi * CW[OFF_C3 + (m+1)*3 + 2];
    }

    col0 = 1.f / (1.f + expf(-col0));
    col1 = 1.f / (1.f + expf(-col1));
    col2 = 1.f / (1.f + expf(-col2));

    float4 r; r.x = col0; r.y = col1; r.z = col2; r.w = sigma;
    ((float4*)out)[i] = r;
}

extern "C" void kernel_launch(void* const* d_in, const int* in_sizes, int n_in,
                              void* d_out, int out_size) {
    const float* x     = (const float*)d_in[0];
    const float* grids = (const float*)d_in[1];
    const float* ws1   = (const float*)d_in[2];
    const float* ws2   = (const float*)d_in[3];
    const float* wc1   = (const float*)d_in[4];
    const float* wc2   = (const float*)d_in[5];
    const float* wc3   = (const float*)d_in[6];
    float* out = (float*)d_out;

    // pack all weights into one device buffer, then ONE memcpy node to const.
    pack_weights<<<(W_TOTAL + 255) / 256, 256>>>(ws1, ws2, wc1, wc2, wc3);
    void* wpack_ptr = nullptr;
    cudaGetSymbolAddress(&wpack_ptr, WPACK);
    cudaMemcpyToSymbolAsync(CW, wpack_ptr, W_TOTAL * sizeof(float), 0,
                            cudaMemcpyDeviceToDevice, 0);

    const int N = in_sizes[0] / 19;
    const int blocks = (N + 127) / 128;
    nerf_fused<<<blocks, 128>>>(x, grids, ws1, ws2, wc1, wc2, out, N);
}